// round 15
// baseline (speedup 1.0000x reference)
#include <cuda_runtime.h>
#include <cstdint>

// Problem constants
constexpr int Hd = 1024;   // hidden
constexpr int Ff = 4096;   // intermediate
constexpr int NE = 8;      // experts
constexpr int NT = 2048;   // tokens
constexpr int NA = 2 * NT; // assignments (top-2)

// ---------------- device scratch (no allocations allowed) ----------------
__device__ int   g_cnt[NE];
__device__ int   g_tok[NE][NT];
__device__ float g_wt[NE][NT];
__device__ int   g_slot[NE][NT];
__device__ float g_xt[(size_t)NT * Hd];      // x, tf32-rounded + k-interleaved
__device__ float g_h[(size_t)NA * Ff];       // intermediate, rounded + interleaved
__device__ float g_sbuf[2 * NT * Hd];        // per-rank-slot output buffers
__device__ float g_wgt[(size_t)NE * Ff * Hd]; // Wg  [e][n][k-intl], rounded
__device__ float g_wut[(size_t)NE * Ff * Hd]; // Wu  [e][n][k-intl], rounded
__device__ float g_wdt[(size_t)NE * Hd * Ff]; // Wd  [e][n][k-intl], rounded

// ---------------- helpers ----------------
__device__ __forceinline__ float f2tf(float x) {
    unsigned u;
    asm("cvt.rna.tf32.f32 %0, %1;" : "=r"(u) : "f"(x));
    return __uint_as_float(u);
}
__device__ __forceinline__ void mma8(float c[4],
                                     unsigned a0, unsigned a1, unsigned a2, unsigned a3,
                                     unsigned b0, unsigned b1) {
    asm volatile(
        "mma.sync.aligned.m16n8k8.row.col.f32.tf32.tf32.f32 "
        "{%0,%1,%2,%3},{%4,%5,%6,%7},{%8,%9},{%0,%1,%2,%3};"
        : "+f"(c[0]), "+f"(c[1]), "+f"(c[2]), "+f"(c[3])
        : "r"(a0), "r"(a1), "r"(a2), "r"(a3), "r"(b0), "r"(b1));
}
__device__ __forceinline__ unsigned s2u(const void* p) {
    unsigned a;
    asm("{ .reg .u64 t; cvta.to.shared.u64 t, %1; cvt.u32.u64 %0, t; }" : "=r"(a) : "l"(p));
    return a;
}
__device__ __forceinline__ void cp16(unsigned d, const float* s) {
    asm volatile("cp.async.cg.shared.global [%0], [%1], 16;" :: "r"(d), "l"(s));
}
#define CP_COMMIT() asm volatile("cp.async.commit_group;" ::: "memory")

// ---------------- small kernels ----------------
__global__ void zero_kernel() {
    if (threadIdx.x < NE) g_cnt[threadIdx.x] = 0;
}

// x -> g_xt: tf32 round + k-interleave (word = 4*(k%4)+k/4 within 16-k group)
__global__ void xprep_kernel(const float* __restrict__ x) {
    int idx = blockIdx.x * 256 + threadIdx.x;
    if (idx < NT * Hd) {
        int row = idx >> 10, k = idx & 1023;
        int w = (k & ~15) + 4 * (k & 3) + ((k & 15) >> 2);
        g_xt[(size_t)row * Hd + w] = f2tf(x[idx]);
    }
}

// Weights: [e][k][n] -> [e][n][k-interleaved], tf32-rounded. 32x32 smem transpose.
__global__ void wprep_kernel(const float* __restrict__ wg,
                             const float* __restrict__ wu,
                             const float* __restrict__ wd) {
    __shared__ float s[32][33];
    int bid = blockIdx.x;
    int tensor = bid >> 15;          // 32768 tiles per tensor
    int r = bid & 32767;
    int ee = r >> 12;                // 4096 tiles per expert
    int rr = r & 4095;

    const float* src;
    float* dst;
    int K, N, tk, tn;
    if (tensor == 0) {
        src = wg + (size_t)ee * Hd * Ff; dst = g_wgt + (size_t)ee * Ff * Hd;
        K = Hd; N = Ff; tk = rr >> 7; tn = rr & 127;
    } else if (tensor == 1) {
        src = wu + (size_t)ee * Hd * Ff; dst = g_wut + (size_t)ee * Ff * Hd;
        K = Hd; N = Ff; tk = rr >> 7; tn = rr & 127;
    } else {
        src = wd + (size_t)ee * Ff * Hd; dst = g_wdt + (size_t)ee * Hd * Ff;
        K = Ff; N = Hd; tk = rr >> 5; tn = rr & 31;
    }
    int tx = threadIdx.x & 31, ty = threadIdx.x >> 5;
#pragma unroll
    for (int i = 0; i < 4; i++)
        s[ty + 8 * i][tx] = f2tf(src[(size_t)(tk * 32 + ty + 8 * i) * N + tn * 32 + tx]);
    __syncthreads();
    // output word tx holds source k-local = interleave-inverse(tx) (self-inverse map)
    int ko = (tx & 16) + 4 * (tx & 3) + ((tx & 15) >> 2);
#pragma unroll
    for (int i = 0; i < 4; i++)
        dst[(size_t)(tn * 32 + ty + 8 * i) * K + tk * 32 + tx] = s[ko][ty + 8 * i];
}

// One warp per token: logits -> softmax -> top-2 -> softmax of the two PROBS.
__global__ void router_kernel(const float* __restrict__ x, const float* __restrict__ gw) {
    int tok  = blockIdx.x * 8 + (threadIdx.x >> 5);
    int lane = threadIdx.x & 31;
    if (tok >= NT) return;
    const float* xr = x + (size_t)tok * Hd;

    float acc[NE];
#pragma unroll
    for (int e = 0; e < NE; e++) acc[e] = 0.f;
    for (int i = lane; i < Hd; i += 32) {
        float xv = xr[i];
        const float* g = gw + i * NE;
#pragma unroll
        for (int e = 0; e < NE; e++) acc[e] = fmaf(xv, g[e], acc[e]);
    }
#pragma unroll
    for (int e = 0; e < NE; e++) {
#pragma unroll
        for (int o = 16; o > 0; o >>= 1) acc[e] += __shfl_xor_sync(0xffffffffu, acc[e], o);
    }
    if (lane == 0) {
        float m = acc[0];
#pragma unroll
        for (int e = 1; e < NE; e++) m = fmaxf(m, acc[e]);
        float p[NE], s = 0.f;
#pragma unroll
        for (int e = 0; e < NE; e++) { p[e] = expf(acc[e] - m); s += p[e]; }
        float inv = 1.f / s;
#pragma unroll
        for (int e = 0; e < NE; e++) p[e] *= inv;

        int i0 = 0;
#pragma unroll
        for (int e = 1; e < NE; e++) if (p[e] > p[i0]) i0 = e;
        int i1 = (i0 == 0) ? 1 : 0;
#pragma unroll
        for (int e = 0; e < NE; e++) if (e != i0 && p[e] > p[i1]) i1 = e;

        float eb = expf(p[i1] - p[i0]);       // <= 1
        float w0 = 1.f / (1.f + eb);
        float w1 = 1.f - w0;

        int s0 = atomicAdd(&g_cnt[i0], 1);
        g_tok[i0][s0] = tok; g_wt[i0][s0] = w0; g_slot[i0][s0] = 0;
        int s1 = atomicAdd(&g_cnt[i1], 1);
        g_tok[i1][s1] = tok; g_wt[i1][s1] = w1; g_slot[i1][s1] = 1;
    }
}

// ============================================================================
// Both GEMMs: all tiles are [rows][16 k-words], pre-rounded + pre-interleaved
// in gmem -> identity cp.async staging, zero cvt. Fragments: LDS.128 only.
// A frag: row R, word 4*qc -> k = qc, qc+4 (ks0: .x/.y), qc+8, qc+12 (ks1: .z/.w)
// B frag: row n, word 4*qc -> b0/b1 for ks0 (.x/.y), ks1 (.z/.w)
// 3-stage cp.async pipeline, one __syncthreads per k-tile:
//   wait(kt) -> sync -> issue(kt+2) -> compute(kt)    [issue target = buffer
//   consumed in iteration kt-1, which every warp finished before this sync]
// ============================================================================

// GEMM1: CTA 128(M) x 64(N) fused gate+up, 128 thr, warps 2x2 (64x32 per matrix)
__global__ void __launch_bounds__(128, 2) gemm1_kernel() {
    int e = blockIdx.z;
    int cnt = g_cnt[e];
    int row0 = blockIdx.y * 128;
    if (row0 >= cnt) return;
    int col0 = blockIdx.x * 64;

    __shared__ __align__(16) float sA[3][2048];
    __shared__ __align__(16) float sG[3][1024];
    __shared__ __align__(16) float sU[3][1024];

    int t = threadIdx.x, lane = t & 31, warp = t >> 5;
    int wm = warp >> 1, wn = warp & 1;
    int qr = lane >> 2, qc = lane & 3;
    int c = t & 3, r0 = t >> 2;

    const float* srcA[4];
#pragma unroll
    for (int j = 0; j < 4; j++) {
        int r = row0 + r0 + 32 * j;
        int rr = (r < cnt) ? r : 0;   // clamp: garbage rows never stored
        srcA[j] = g_xt + (size_t)g_tok[e][rr] * Hd + 4 * c;
    }
    const float *srcG[2], *srcU[2];
#pragma unroll
    for (int j = 0; j < 2; j++) {
        int n = col0 + r0 + 32 * j;
        srcG[j] = g_wgt + ((size_t)e * Ff + n) * Hd + 4 * c;
        srcU[j] = g_wut + ((size_t)e * Ff + n) * Hd + 4 * c;
    }
    unsigned dA = s2u(&sA[0][0]) + (unsigned)((r0 * 16 + 4 * c) * 4);
    unsigned dG = s2u(&sG[0][0]) + (unsigned)((r0 * 16 + 4 * c) * 4);
    unsigned dU = s2u(&sU[0][0]) + (unsigned)((r0 * 16 + 4 * c) * 4);

    auto issue = [&](int kt) {
        int buf = kt % 3;
        int ko = kt * 16;
        unsigned bA = dA + buf * 8192, bG = dG + buf * 4096, bU = dU + buf * 4096;
#pragma unroll
        for (int j = 0; j < 4; j++) cp16(bA + j * 2048, srcA[j] + ko);
#pragma unroll
        for (int j = 0; j < 2; j++) cp16(bG + j * 2048, srcG[j] + ko);
#pragma unroll
        for (int j = 0; j < 2; j++) cp16(bU + j * 2048, srcU[j] + ko);
        CP_COMMIT();
    };

    float accG[4][4][4], accU[4][4][4];
#pragma unroll
    for (int a = 0; a < 4; a++)
#pragma unroll
        for (int b = 0; b < 4; b++)
#pragma unroll
            for (int d = 0; d < 4; d++) { accG[a][b][d] = 0.f; accU[a][b][d] = 0.f; }

    issue(0); issue(1);
    const int KT = Hd / 16;   // 64
    for (int kt = 0; kt < KT; kt++) {
        if (kt + 1 < KT) asm volatile("cp.async.wait_group 1;" ::: "memory");
        else             asm volatile("cp.async.wait_group 0;" ::: "memory");
        __syncthreads();
        if (kt + 2 < KT) issue(kt + 2);
        int buf = kt % 3;

        uint4 alo[4], ahi[4];
#pragma unroll
        for (int mt = 0; mt < 4; mt++) {
            int R = wm * 64 + mt * 16 + qr;
            alo[mt] = *(const uint4*)&sA[buf][R * 16 + 4 * qc];
            ahi[mt] = *(const uint4*)&sA[buf][(R + 8) * 16 + 4 * qc];
        }
#pragma unroll
        for (int half = 0; half < 2; half++) {
            uint4 gq[2], uq[2];
#pragma unroll
            for (int n2 = 0; n2 < 2; n2++) {
                int n = wn * 32 + (half * 2 + n2) * 8 + qr;
                gq[n2] = *(const uint4*)&sG[buf][n * 16 + 4 * qc];
                uq[n2] = *(const uint4*)&sU[buf][n * 16 + 4 * qc];
            }
#pragma unroll
            for (int n2 = 0; n2 < 2; n2++) {
                int nt = half * 2 + n2;
#pragma unroll
                for (int mt = 0; mt < 4; mt++)
                    mma8(accG[mt][nt], alo[mt].x, ahi[mt].x, alo[mt].y, ahi[mt].y, gq[n2].x, gq[n2].y);
#pragma unroll
                for (int mt = 0; mt < 4; mt++)
                    mma8(accG[mt][nt], alo[mt].z, ahi[mt].z, alo[mt].w, ahi[mt].w, gq[n2].z, gq[n2].w);
#pragma unroll
                for (int mt = 0; mt < 4; mt++)
                    mma8(accU[mt][nt], alo[mt].x, ahi[mt].x, alo[mt].y, ahi[mt].y, uq[n2].x, uq[n2].y);
#pragma unroll
                for (int mt = 0; mt < 4; mt++)
                    mma8(accU[mt][nt], alo[mt].z, ahi[mt].z, alo[mt].w, ahi[mt].w, uq[n2].z, uq[n2].w);
            }
        }
    }

    // epilogue: h = silu(g) * u -> g_h[tok*2+slot], tf32-rounded + k-interleaved
#pragma unroll
    for (int mt = 0; mt < 4; mt++) {
#pragma unroll
        for (int half = 0; half < 2; half++) {
            int r = row0 + wm * 64 + mt * 16 + qr + half * 8;
            if (r < cnt) {
                int aid = g_tok[e][r] * 2 + g_slot[e][r];
                float* hrow = g_h + (size_t)aid * Ff + col0;
#pragma unroll
                for (int nt = 0; nt < 4; nt++) {
                    float gg0 = accG[mt][nt][half * 2 + 0], gg1 = accG[mt][nt][half * 2 + 1];
                    float uu0 = accU[mt][nt][half * 2 + 0], uu1 = accU[mt][nt][half * 2 + 1];
                    float h0 = gg0 * uu0 / (1.f + __expf(-gg0));
                    float h1 = gg1 * uu1 / (1.f + __expf(-gg1));
                    int cc = wn * 32 + nt * 8 + 2 * qc;          // even
                    int i0 = cc & 15;
                    int w0 = (cc & ~15) + 4 * (i0 & 3) + (i0 >> 2);
                    hrow[w0]     = f2tf(h0);
                    hrow[w0 + 4] = f2tf(h1);
                }
            }
        }
    }
}

// GEMM2: CTA 128(M) x 128(N), 128 thr, warps 2x2 (64x64)
__global__ void __launch_bounds__(128, 2) gemm2_kernel() {
    int e = blockIdx.z;
    int cnt = g_cnt[e];
    int row0 = blockIdx.y * 128;
    if (row0 >= cnt) return;
    int col0 = blockIdx.x * 128;

    __shared__ __align__(16) float sA[3][2048];
    __shared__ __align__(16) float sB[3][2048];

    int t = threadIdx.x, lane = t & 31, warp = t >> 5;
    int wm = warp >> 1, wn = warp & 1;
    int qr = lane >> 2, qc = lane & 3;
    int c = t & 3, r0 = t >> 2;

    const float* srcA[4];
#pragma unroll
    for (int j = 0; j < 4; j++) {
        int r = row0 + r0 + 32 * j;
        int rr = (r < cnt) ? r : 0;
        int aid = g_tok[e][rr] * 2 + g_slot[e][rr];
        srcA[j] = g_h + (size_t)aid * Ff + 4 * c;
    }
    const float* srcB[4];
#pragma unroll
    for (int j = 0; j < 4; j++) {
        int n = col0 + r0 + 32 * j;
        srcB[j] = g_wdt + ((size_t)e * Hd + n) * Ff + 4 * c;
    }
    unsigned dA = s2u(&sA[0][0]) + (unsigned)((r0 * 16 + 4 * c) * 4);
    unsigned dB = s2u(&sB[0][0]) + (unsigned)((r0 * 16 + 4 * c) * 4);

    auto issue = [&](int kt) {
        int buf = kt % 3;
        int ko = kt * 16;
        unsigned bA = dA + buf * 8192, bB = dB + buf * 8192;
#pragma unroll
        for (int j = 0; j < 4; j++) cp16(bA + j * 2048, srcA[j] + ko);
#pragma unroll
        for (int j = 0; j < 4; j++) cp16(bB + j * 2048, srcB[j] + ko);
        CP_COMMIT();
    };

    float acc[4][8][4];
#pragma unroll
    for (int a = 0; a < 4; a++)
#pragma unroll
        for (int b = 0; b < 8; b++)
#pragma unroll
            for (int d = 0; d < 4; d++) acc[a][b][d] = 0.f;

    issue(0); issue(1);
    const int KT = Ff / 16;   // 256
    for (int kt = 0; kt < KT; kt++) {
        if (kt + 1 < KT) asm volatile("cp.async.wait_group 1;" ::: "memory");
        else             asm volatile("cp.async.wait_group 0;" ::: "memory");
        __syncthreads();
        if (kt + 2 < KT) issue(kt + 2);
        int buf = kt % 3;

        uint4 alo[4], ahi[4];
#pragma unroll
        for (int mt = 0; mt < 4; mt++) {
            int R = wm * 64 + mt * 16 + qr;
            alo[mt] = *(const uint4*)&sA[buf][R * 16 + 4 * qc];
            ahi[mt] = *(const uint4*)&sA[buf][(R + 8) * 16 + 4 * qc];
        }
#pragma unroll
        for (int half = 0; half < 2; half++) {
            uint4 bq[4];
#pragma unroll
            for (int n2 = 0; n2 < 4; n2++) {
                int n = wn * 64 + (half * 4 + n2) * 8 + qr;
                bq[n2] = *(const uint4*)&sB[buf][n * 16 + 4 * qc];
            }
#pragma unroll
            for (int n2 = 0; n2 < 4; n2++) {
                int nt = half * 4 + n2;
#pragma unroll
                for (int mt = 0; mt < 4; mt++)
                    mma8(acc[mt][nt], alo[mt].x, ahi[mt].x, alo[mt].y, ahi[mt].y, bq[n2].x, bq[n2].y);
#pragma unroll
                for (int mt = 0; mt < 4; mt++)
                    mma8(acc[mt][nt], alo[mt].z, ahi[mt].z, alo[mt].w, ahi[mt].w, bq[n2].z, bq[n2].w);
            }
        }
    }

#pragma unroll
    for (int mt = 0; mt < 4; mt++) {
#pragma unroll
        for (int half = 0; half < 2; half++) {
            int r = row0 + wm * 64 + mt * 16 + qr + half * 8;
            if (r < cnt) {
                int tok = g_tok[e][r];
                float w = g_wt[e][r];
                int sl  = g_slot[e][r];
                float* orow = g_sbuf + (size_t)sl * NT * Hd + (size_t)tok * Hd + col0;
#pragma unroll
                for (int nt = 0; nt < 8; nt++) {
                    int cc = wn * 64 + nt * 8 + 2 * qc;
                    *(float2*)(orow + cc) = make_float2(w * acc[mt][nt][half * 2 + 0],
                                                        w * acc[mt][nt][half * 2 + 1]);
                }
            }
        }
    }
}

__global__ void combine_kernel(float* __restrict__ out) {
    int i = blockIdx.x * 256 + threadIdx.x;
    if (i < NT * Hd / 4) {
        float4 a = ((const float4*)g_sbuf)[i];
        float4 b = ((const float4*)(g_sbuf + NT * Hd))[i];
        ((float4*)out)[i] = make_float4(a.x + b.x, a.y + b.y, a.z + b.z, a.w + b.w);
    }
}

// ---------------- launch ----------------
extern "C" void kernel_launch(void* const* d_in, const int* in_sizes, int n_in,
                              void* d_out, int out_size) {
    (void)in_sizes; (void)n_in; (void)out_size;
    const float* x      = (const float*)d_in[0];
    const float* gw     = (const float*)d_in[1];
    const float* w_gate = (const float*)d_in[2];
    const float* w_up   = (const float*)d_in[3];
    const float* w_down = (const float*)d_in[4];
    float* out = (float*)d_out;

    zero_kernel<<<1, 32>>>();
    wprep_kernel<<<3 * 32768, 256>>>(w_gate, w_up, w_down);
    xprep_kernel<<<(NT * Hd) / 256, 256>>>(x);
    router_kernel<<<NT / 8, 256>>>(x, gw);
    gemm1_kernel<<<dim3(Ff / 64, NT / 128, NE), 128>>>();
    gemm2_kernel<<<dim3(Hd / 128, NT / 128, NE), 128>>>();
    combine_kernel<<<(NT * Hd / 4 + 255) / 256, 256>>>(out);
}